// round 1
// baseline (speedup 1.0000x reference)
#include <cuda_runtime.h>
#include <math.h>

#define BB   2
#define SS   2048
#define DD   1024
#define HH   16
#define DKK  64
#define DFFN 4096
#define NTOK (BB*SS)

// ---- scratch (device globals; no runtime allocation) ----
__device__ float g_xn[NTOK*DD];
__device__ float g_q [NTOK*DD];
__device__ float g_k [NTOK*DD];
__device__ float g_v [NTOK*DD];
__device__ float g_ctx[NTOK*DD];
__device__ float g_x1[NTOK*DD];
__device__ float g_h [NTOK*DFFN];
__device__ float g_scores[(size_t)BB*HH*SS*SS];   // 536 MB

// ============================================================
// LayerNorm: per row of 1024. unbiased std (ddof=1), /(std+eps)
// ============================================================
__global__ __launch_bounds__(256) void ln_kernel(
    const float* __restrict__ x, float* __restrict__ out,
    const float* __restrict__ g, const float* __restrict__ b)
{
    __shared__ float red[256];
    int row = blockIdx.x;
    int tid = threadIdx.x;
    const float* xr = x + (size_t)row * DD;

    float v[4];
    float s = 0.f;
#pragma unroll
    for (int i = 0; i < 4; i++) { v[i] = xr[tid + i*256]; s += v[i]; }
    red[tid] = s; __syncthreads();
    for (int o = 128; o > 0; o >>= 1) {
        if (tid < o) red[tid] += red[tid + o];
        __syncthreads();
    }
    float mean = red[0] / (float)DD;
    __syncthreads();

    float vs = 0.f;
#pragma unroll
    for (int i = 0; i < 4; i++) { float d = v[i] - mean; vs += d*d; }
    red[tid] = vs; __syncthreads();
    for (int o = 128; o > 0; o >>= 1) {
        if (tid < o) red[tid] += red[tid + o];
        __syncthreads();
    }
    float var = red[0] / (float)(DD - 1);
    float inv = 1.f / (sqrtf(var) + 1e-6f);
    float g0 = g[0], b0 = b[0];
    float* orow = out + (size_t)row * DD;
#pragma unroll
    for (int i = 0; i < 4; i++)
        orow[tid + i*256] = g0 * (v[i] - mean) * inv + b0;
}

// ============================================================
// Row softmax over length SS (2048), in place
// ============================================================
__global__ __launch_bounds__(256) void softmax_kernel(float* __restrict__ sc)
{
    __shared__ float red[256];
    size_t row = blockIdx.x;
    float* p = sc + row * (size_t)SS;
    int tid = threadIdx.x;

    float v[8];
    float mx = -1e30f;
#pragma unroll
    for (int i = 0; i < 8; i++) { v[i] = p[tid + i*256]; mx = fmaxf(mx, v[i]); }
    red[tid] = mx; __syncthreads();
    for (int o = 128; o > 0; o >>= 1) {
        if (tid < o) red[tid] = fmaxf(red[tid], red[tid + o]);
        __syncthreads();
    }
    mx = red[0]; __syncthreads();

    float s = 0.f;
#pragma unroll
    for (int i = 0; i < 8; i++) { v[i] = expf(v[i] - mx); s += v[i]; }
    red[tid] = s; __syncthreads();
    for (int o = 128; o > 0; o >>= 1) {
        if (tid < o) red[tid] += red[tid + o];
        __syncthreads();
    }
    float inv = 1.f / red[0];
#pragma unroll
    for (int i = 0; i < 8; i++) p[tid + i*256] = v[i] * inv;
}

// ============================================================
// Generic batched SGEMM: C = alpha*(A @ B[^T]) [+bias] [mask->-1] [+resid] [relu]
// Batch z decomposed as (bz, hz) = (z/HH, z%HH) with separate strides.
// 128x128x8 tile, 256 threads, 8x8 per thread.
// ============================================================
#define BM 128
#define BN 128
#define BK 8

__global__ __launch_bounds__(256) void sgemm(
    const float* __restrict__ A, const float* __restrict__ B, float* __restrict__ C,
    const float* __restrict__ bias, const float* __restrict__ resid,
    const int* __restrict__ mask,
    int M, int N, int K, int lda, int ldb, int ldc,
    long sAb, long sAh, long sBb, long sBh, long sCb, long sCh,
    float alpha, int transB, int relu)
{
    __shared__ float As[BK][BM];
    __shared__ float Bs[BK][BN];

    int z  = blockIdx.z;
    int bz = z / HH, hz = z % HH;
    const float* Ab = A + bz*sAb + hz*sAh;
    const float* Bb = B + bz*sBb + hz*sBh;
    float*       Cb = C + bz*sCb + hz*sCh;

    int rowStart = blockIdx.y * BM;
    int colStart = blockIdx.x * BN;
    int tid  = threadIdx.x;
    int tRow = tid >> 4;     // 0..15
    int tCol = tid & 15;     // 0..15

    float acc[8][8];
#pragma unroll
    for (int i = 0; i < 8; i++)
#pragma unroll
        for (int j = 0; j < 8; j++) acc[i][j] = 0.f;

    int aR = tid >> 1;          // 0..127
    int aC = (tid & 1) * 4;     // 0 / 4

    for (int k0 = 0; k0 < K; k0 += BK) {
        // A tile: [BM x BK] -> As[k][m]
        {
            int gr = rowStart + aR;
            float4 av = make_float4(0.f, 0.f, 0.f, 0.f);
            if (gr < M)
                av = *reinterpret_cast<const float4*>(Ab + (size_t)gr*lda + k0 + aC);
            As[aC+0][aR] = av.x; As[aC+1][aR] = av.y;
            As[aC+2][aR] = av.z; As[aC+3][aR] = av.w;
        }
        // B tile -> Bs[k][n]
        if (!transB) {
            int bk = tid >> 5;           // 0..7
            int bn = (tid & 31) * 4;     // 0..124
            float4 bv = make_float4(0.f, 0.f, 0.f, 0.f);
            int gn = colStart + bn;
            if (gn < N)
                bv = *reinterpret_cast<const float4*>(Bb + (size_t)(k0+bk)*ldb + gn);
            *reinterpret_cast<float4*>(&Bs[bk][bn]) = bv;
        } else {
            int bn = tid >> 1;           // 0..127 (N index)
            int bk = (tid & 1) * 4;      // 0 / 4
            float4 bv = make_float4(0.f, 0.f, 0.f, 0.f);
            int gn = colStart + bn;
            if (gn < N)
                bv = *reinterpret_cast<const float4*>(Bb + (size_t)gn*ldb + k0 + bk);
            Bs[bk+0][bn] = bv.x; Bs[bk+1][bn] = bv.y;
            Bs[bk+2][bn] = bv.z; Bs[bk+3][bn] = bv.w;
        }
        __syncthreads();

#pragma unroll
        for (int k = 0; k < BK; k++) {
            float4 a0 = *reinterpret_cast<const float4*>(&As[k][tRow*8]);
            float4 a1 = *reinterpret_cast<const float4*>(&As[k][tRow*8+4]);
            float4 b0 = *reinterpret_cast<const float4*>(&Bs[k][tCol*8]);
            float4 b1 = *reinterpret_cast<const float4*>(&Bs[k][tCol*8+4]);
            float ra[8] = {a0.x,a0.y,a0.z,a0.w,a1.x,a1.y,a1.z,a1.w};
            float rb[8] = {b0.x,b0.y,b0.z,b0.w,b1.x,b1.y,b1.z,b1.w};
#pragma unroll
            for (int i = 0; i < 8; i++)
#pragma unroll
                for (int j = 0; j < 8; j++)
                    acc[i][j] += ra[i] * rb[j];
        }
        __syncthreads();
    }

    const int* mrow = mask ? (mask + (size_t)bz * SS) : nullptr;
#pragma unroll
    for (int i = 0; i < 8; i++) {
        int r = rowStart + tRow*8 + i;
        if (r >= M) continue;
#pragma unroll
        for (int j = 0; j < 8; j++) {
            int c = colStart + tCol*8 + j;
            if (c >= N) continue;
            float v = alpha * acc[i][j];
            if (bias) v += bias[c];
            if (mrow && mrow[c] == 0) v = -1.0f;           // MASK_FILL (precedence bug)
            if (resid) v += resid[(size_t)r*ldc + c];
            if (relu)  v = fmaxf(v, 0.f);
            Cb[(size_t)r*ldc + c] = v;
        }
    }
}

// ============================================================
static inline void launch_gemm(
    const float* A, const float* B, float* C,
    const float* bias, const float* resid, const int* mask,
    int M, int N, int K, int lda, int ldb, int ldc,
    long sAb, long sAh, long sBb, long sBh, long sCb, long sCh,
    int batch, float alpha, int transB, int relu)
{
    dim3 grid((N + BN - 1)/BN, (M + BM - 1)/BM, batch);
    sgemm<<<grid, 256>>>(A, B, C, bias, resid, mask,
                         M, N, K, lda, ldb, ldc,
                         sAb, sAh, sBb, sBh, sCb, sCh,
                         alpha, transB, relu);
}

extern "C" void kernel_launch(void* const* d_in, const int* in_sizes, int n_in,
                              void* d_out, int out_size)
{
    const float* x    = (const float*)d_in[0];
    const int*   msk  = (const int*)  d_in[1];
    const float* wq   = (const float*)d_in[2];
    const float* bq   = (const float*)d_in[3];
    const float* wk   = (const float*)d_in[4];
    const float* bk   = (const float*)d_in[5];
    const float* wv   = (const float*)d_in[6];
    const float* bv   = (const float*)d_in[7];
    const float* wo   = (const float*)d_in[8];
    const float* bo   = (const float*)d_in[9];
    const float* w1   = (const float*)d_in[10];
    const float* b1   = (const float*)d_in[11];
    const float* w2   = (const float*)d_in[12];
    const float* b2   = (const float*)d_in[13];
    const float* g1   = (const float*)d_in[14];
    const float* be1  = (const float*)d_in[15];
    const float* g2   = (const float*)d_in[16];
    const float* be2  = (const float*)d_in[17];
    float* out = (float*)d_out;

    float *xn, *q, *k, *v, *ctx, *x1, *hb, *sc;
    cudaGetSymbolAddress((void**)&xn,  g_xn);
    cudaGetSymbolAddress((void**)&q,   g_q);
    cudaGetSymbolAddress((void**)&k,   g_k);
    cudaGetSymbolAddress((void**)&v,   g_v);
    cudaGetSymbolAddress((void**)&ctx, g_ctx);
    cudaGetSymbolAddress((void**)&x1,  g_x1);
    cudaGetSymbolAddress((void**)&hb,  g_h);
    cudaGetSymbolAddress((void**)&sc,  g_scores);

    // 1) LN1
    ln_kernel<<<NTOK, 256>>>(x, xn, g1, be1);

    // 2) Q, K, V projections (kept in [B,S,H,DK] contiguous as [NTOK, D])
    launch_gemm(xn, wq, q, bq, nullptr, nullptr, NTOK, DD, DD, DD, DD, DD,
                0,0,0,0,0,0, 1, 1.f, 0, 0);
    launch_gemm(xn, wk, k, bk, nullptr, nullptr, NTOK, DD, DD, DD, DD, DD,
                0,0,0,0,0,0, 1, 1.f, 0, 0);
    launch_gemm(xn, wv, v, bv, nullptr, nullptr, NTOK, DD, DD, DD, DD, DD,
                0,0,0,0,0,0, 1, 1.f, 0, 0);

    // 3) scores[b,h] = (Q @ K^T) / 8, masked -> -1.0 where mask==0
    launch_gemm(q, k, sc, nullptr, nullptr, msk,
                SS, SS, DKK, DD, DD, SS,
                (long)SS*DD, DKK, (long)SS*DD, DKK,
                (long)HH*SS*SS, (long)SS*SS,
                BB*HH, 0.125f, 1, 0);

    // 4) softmax rows
    softmax_kernel<<<BB*HH*SS, 256>>>(sc);

    // 5) ctx[b,h] = attn @ V   (written back in [B,S,H,DK] layout)
    launch_gemm(sc, v, ctx, nullptr, nullptr, nullptr,
                SS, DKK, SS, SS, DD, DD,
                (long)HH*SS*SS, (long)SS*SS, (long)SS*DD, DKK,
                (long)SS*DD, DKK,
                BB*HH, 1.f, 0, 0);

    // 6) x1 = x + ctx @ wo + bo
    launch_gemm(ctx, wo, x1, bo, x, nullptr, NTOK, DD, DD, DD, DD, DD,
                0,0,0,0,0,0, 1, 1.f, 0, 0);

    // 7) LN2
    ln_kernel<<<NTOK, 256>>>(x1, xn, g2, be2);

    // 8) h = relu(xn @ w1 + b1)
    launch_gemm(xn, w1, hb, b1, nullptr, nullptr, NTOK, DFFN, DD, DD, DFFN, DFFN,
                0,0,0,0,0,0, 1, 1.f, 0, 1);

    // 9) out = x1 + h @ w2 + b2
    launch_gemm(hb, w2, out, b2, x1, nullptr, NTOK, DD, DFFN, DFFN, DD, DD,
                0,0,0,0,0,0, 1, 1.f, 0, 0);
}

// round 4
// speedup vs baseline: 3.0858x; 3.0858x over previous
#include <cuda_runtime.h>
#include <cstdint>
#include <math.h>

#define BB   2
#define SS   2048
#define DD   1024
#define HH   16
#define DKK  64
#define DFFN 4096
#define NTOK (BB*SS)

// ---------------- persistent scratch (no runtime allocation) ----------------
__device__ float g_xn [NTOK*DD];
__device__ float g_q  [NTOK*DD];
__device__ float g_k  [NTOK*DD];
__device__ float g_vT [(size_t)BB*DD*SS];      // V transposed: [b, d, s]
__device__ float g_ctx[NTOK*DD];
__device__ float g_x1 [NTOK*DD];
__device__ float g_h  [NTOK*DFFN];
__device__ float g_scores[(size_t)BB*HH*SS*SS];
__device__ float g_wqT[DD*DD];
__device__ float g_wkT[DD*DD];
__device__ float g_wvT[DD*DD];
__device__ float g_woT[DD*DD];
__device__ float g_w1T[(size_t)DFFN*DD];
__device__ float g_w2T[(size_t)DD*DFFN];

// ---------------- helpers ----------------
__device__ __forceinline__ float tf32r(float x){
    uint32_t u; asm("cvt.rna.tf32.f32 %0, %1;" : "=r"(u) : "f"(x));
    return __uint_as_float(u);
}
__device__ __forceinline__ uint32_t smem_u32(const void* p){
    uint32_t a;
    asm("{ .reg .u64 t; cvta.to.shared.u64 t, %1; cvt.u32.u64 %0, t; }" : "=r"(a) : "l"(p));
    return a;
}
__device__ __forceinline__ void cp16(uint32_t dst, const float* src){
    asm volatile("cp.async.cg.shared.global [%0], [%1], 16;"
                 :: "r"(dst), "l"(__cvta_generic_to_global(src)) : "memory");
}

// ---------------- LayerNorm (ddof=1, /(std+eps)); output tf32-rounded ----------------
__global__ __launch_bounds__(256) void ln_kernel(
    const float* __restrict__ x, float* __restrict__ out,
    const float* __restrict__ g, const float* __restrict__ b)
{
    __shared__ float red[256];
    int row = blockIdx.x;
    int tid = threadIdx.x;
    const float* xr = x + (size_t)row * DD;

    float v[4]; float s = 0.f;
#pragma unroll
    for (int i = 0; i < 4; i++) { v[i] = xr[tid + i*256]; s += v[i]; }
    red[tid] = s; __syncthreads();
    for (int o = 128; o > 0; o >>= 1) { if (tid < o) red[tid] += red[tid+o]; __syncthreads(); }
    float mean = red[0] / (float)DD;
    __syncthreads();

    float vs = 0.f;
#pragma unroll
    for (int i = 0; i < 4; i++) { float d = v[i] - mean; vs += d*d; }
    red[tid] = vs; __syncthreads();
    for (int o = 128; o > 0; o >>= 1) { if (tid < o) red[tid] += red[tid+o]; __syncthreads(); }
    float var = red[0] / (float)(DD - 1);
    float inv = 1.f / (sqrtf(var) + 1e-6f);
    float g0 = g[0], b0 = b[0];
    float* orow = out + (size_t)row * DD;
#pragma unroll
    for (int i = 0; i < 4; i++)
        orow[tid + i*256] = tf32r(g0 * (v[i] - mean) * inv + b0);
}

// ---------------- Row softmax, in place; output tf32-rounded ----------------
__global__ __launch_bounds__(256) void softmax_kernel(float* __restrict__ sc)
{
    __shared__ float red[256];
    size_t row = blockIdx.x;
    float* p = sc + row * (size_t)SS;
    int tid = threadIdx.x;

    float v[8]; float mx = -1e30f;
#pragma unroll
    for (int i = 0; i < 8; i++) { v[i] = p[tid + i*256]; mx = fmaxf(mx, v[i]); }
    red[tid] = mx; __syncthreads();
    for (int o = 128; o > 0; o >>= 1) { if (tid < o) red[tid] = fmaxf(red[tid], red[tid+o]); __syncthreads(); }
    mx = red[0]; __syncthreads();

    float s = 0.f;
#pragma unroll
    for (int i = 0; i < 8; i++) { v[i] = expf(v[i] - mx); s += v[i]; }
    red[tid] = s; __syncthreads();
    for (int o = 128; o > 0; o >>= 1) { if (tid < o) red[tid] += red[tid+o]; __syncthreads(); }
    float inv = 1.f / red[0];
#pragma unroll
    for (int i = 0; i < 8; i++) p[tid + i*256] = tf32r(v[i] * inv);
}

// ---------------- weight transpose (tf32-rounded) ----------------
__global__ __launch_bounds__(256) void transpose_kernel(
    const float* __restrict__ in, float* __restrict__ out, int R, int Cc)
{
    __shared__ float t[32][33];
    int c0 = blockIdx.x * 32, r0 = blockIdx.y * 32;
    int x = threadIdx.x, y = threadIdx.y;      // block (32, 8)
#pragma unroll
    for (int i = y; i < 32; i += 8) t[i][x] = in[(size_t)(r0 + i) * Cc + c0 + x];
    __syncthreads();
#pragma unroll
    for (int i = y; i < 32; i += 8) out[(size_t)(c0 + i) * R + r0 + x] = tf32r(t[x][i]);
}

// ============================================================
// tf32 mma.sync GEMM: C[128 x BN] per CTA = alpha*(A @ Bt^T) (+bias)(mask)(+resid)(relu)
// A: [M,K] row-major (lda). Bt: [N,K] row-major (ldb). K % 32 == 0, exact dims.
// Double-buffered cp.async, BK=32, warp tile (MT*16) x (NT*8).
// ============================================================
template<int BN, int WGX, int MT, int NT>
__global__ __launch_bounds__(256)
void mma_gemm(const float* __restrict__ A, const float* __restrict__ Bt,
              float* __restrict__ C, const float* __restrict__ bias,
              const float* __restrict__ resid, const int* __restrict__ mask,
              int K, int lda, int ldb, int ldc,
              long sAb, long sAh, long sBb, long sBh, long sCb, long sCh,
              float alpha, int relu, int storeT, int roundOut)
{
    extern __shared__ float sm[];
    constexpr int ASZ = 128 * 36;          // floats per A stage (pad 4 -> conflict-free frags)
    constexpr int BSZ = BN * 36;
    float* A0 = sm;
    float* B0 = sm + 2 * ASZ;

    const int tid = threadIdx.x;
    const int z = blockIdx.z, bz = z / HH, hz = z - bz * HH;
    const float* Ab = A  + bz * sAb + hz * sAh;
    const float* Bb = Bt + bz * sBb + hz * sBh;
    float*       Cb = C  + bz * sCb + hz * sCh;
    const int rowStart = blockIdx.y * 128;
    const int colStart = blockIdx.x * BN;

    const uint32_t aBase = smem_u32(A0), bBase = smem_u32(B0);

    auto loadA = [&](int buf, int k0){
        uint32_t dst = aBase + (uint32_t)buf * (ASZ * 4);
#pragma unroll
        for (int p = 0; p < 4; p++){
            int slot = tid + p * 256;
            int r = slot >> 3, qq = slot & 7;
            cp16(dst + (uint32_t)(r * 36 + qq * 4) * 4,
                 Ab + (size_t)(rowStart + r) * lda + k0 + qq * 4);
        }
    };
    auto loadB = [&](int buf, int k0){
        uint32_t dst = bBase + (uint32_t)buf * (BSZ * 4);
#pragma unroll
        for (int p = 0; p < BN / 32; p++){
            int slot = tid + p * 256;
            int r = slot >> 3, qq = slot & 7;
            cp16(dst + (uint32_t)(r * 36 + qq * 4) * 4,
                 Bb + (size_t)(colStart + r) * ldb + k0 + qq * 4);
        }
    };

    const int warp = tid >> 5, lane = tid & 31;
    const int g = lane >> 2, qd = lane & 3;
    const int wy = warp / WGX, wx = warp % WGX;
    const int m0 = wy * MT * 16, n0 = wx * NT * 8;

    float acc[MT][NT][4];
#pragma unroll
    for (int mt = 0; mt < MT; mt++)
#pragma unroll
        for (int nt = 0; nt < NT; nt++)
#pragma unroll
            for (int e = 0; e < 4; e++) acc[mt][nt][e] = 0.f;

    const int nk = K >> 5;
    loadA(0, 0); loadB(0, 0);
    asm volatile("cp.async.commit_group;" ::: "memory");

    for (int s = 0; s < nk; s++){
        if (s + 1 < nk){ loadA((s + 1) & 1, (s + 1) * 32); loadB((s + 1) & 1, (s + 1) * 32); }
        asm volatile("cp.async.commit_group;" ::: "memory");
        asm volatile("cp.async.wait_group 1;" ::: "memory");
        __syncthreads();

        const float* As = A0 + (s & 1) * ASZ;
        const float* Bs = B0 + (s & 1) * BSZ;
#pragma unroll
        for (int ks = 0; ks < 32; ks += 8){
            uint32_t af[MT][4], bf[NT][2];
#pragma unroll
            for (int mt = 0; mt < MT; mt++){
                const uint32_t* ap  = (const uint32_t*)(As + (m0 + mt*16 + g    ) * 36 + ks + qd);
                const uint32_t* ap8 = (const uint32_t*)(As + (m0 + mt*16 + g + 8) * 36 + ks + qd);
                af[mt][0] = ap[0];  af[mt][2] = ap[4];
                af[mt][1] = ap8[0]; af[mt][3] = ap8[4];
            }
#pragma unroll
            for (int nt = 0; nt < NT; nt++){
                const uint32_t* bp = (const uint32_t*)(Bs + (n0 + nt*8 + g) * 36 + ks + qd);
                bf[nt][0] = bp[0]; bf[nt][1] = bp[4];
            }
#pragma unroll
            for (int mt = 0; mt < MT; mt++)
#pragma unroll
                for (int nt = 0; nt < NT; nt++)
                    asm volatile(
                        "mma.sync.aligned.m16n8k8.row.col.f32.tf32.tf32.f32 "
                        "{%0,%1,%2,%3}, {%4,%5,%6,%7}, {%8,%9}, {%0,%1,%2,%3};"
                        : "+f"(acc[mt][nt][0]), "+f"(acc[mt][nt][1]),
                          "+f"(acc[mt][nt][2]), "+f"(acc[mt][nt][3])
                        : "r"(af[mt][0]), "r"(af[mt][1]), "r"(af[mt][2]), "r"(af[mt][3]),
                          "r"(bf[nt][0]), "r"(bf[nt][1]));
        }
        __syncthreads();
    }

    // ---------------- epilogue ----------------
    const int* mrow = mask ? (mask + (size_t)bz * SS) : nullptr;
#pragma unroll
    for (int mt = 0; mt < MT; mt++)
#pragma unroll
        for (int nt = 0; nt < NT; nt++)
#pragma unroll
            for (int e = 0; e < 4; e++){
                int r = rowStart + m0 + mt * 16 + g + ((e >= 2) ? 8 : 0);
                int c = colStart + n0 + nt * 8 + qd * 2 + (e & 1);
                float v = alpha * acc[mt][nt][e];
                if (bias)  v += bias[c];
                if (mrow && mrow[c] == 0) v = -1.0f;    // MASK_FILL (precedence bug)
                if (resid) v += resid[(size_t)r * ldc + c];
                if (relu)  v = fmaxf(v, 0.f);
                if (roundOut) v = tf32r(v);
                if (!storeT) {
                    Cb[(size_t)r * ldc + c] = v;
                } else {
                    int bb = r >> 11;            // r / SS
                    int si = r & (SS - 1);
                    C[((size_t)bb * DD + c) * SS + si] = v;
                }
            }
}

// ---------------- host-side launcher ----------------
template<int BN, int WGX, int MT, int NT>
static void run_gemm(const float* A, const float* Bt, float* C,
                     const float* bias, const float* resid, const int* mask,
                     int M, int N, int K, int lda, int ldb, int ldc,
                     long sAb, long sAh, long sBb, long sBh, long sCb, long sCh,
                     int batch, float alpha, int relu, int storeT, int roundOut)
{
    constexpr int SMEM = (2 * 128 * 36 + 2 * BN * 36) * 4;
    cudaFuncSetAttribute(mma_gemm<BN, WGX, MT, NT>,
                         cudaFuncAttributeMaxDynamicSharedMemorySize, SMEM);
    dim3 grid(N / BN, M / 128, batch);
    mma_gemm<BN, WGX, MT, NT><<<grid, 256, SMEM>>>(
        A, Bt, C, bias, resid, mask, K, lda, ldb, ldc,
        sAb, sAh, sBb, sBh, sCb, sCh, alpha, relu, storeT, roundOut);
}

extern "C" void kernel_launch(void* const* d_in, const int* in_sizes, int n_in,
                              void* d_out, int out_size)
{
    const float* x   = (const float*)d_in[0];
    const int*   msk = (const int*)  d_in[1];
    const float* wq  = (const float*)d_in[2];
    const float* bq  = (const float*)d_in[3];
    const float* wk  = (const float*)d_in[4];
    const float* bk  = (const float*)d_in[5];
    const float* wv  = (const float*)d_in[6];
    const float* bv  = (const float*)d_in[7];
    const float* wo  = (const float*)d_in[8];
    const float* bo  = (const float*)d_in[9];
    const float* w1  = (const float*)d_in[10];
    const float* b1  = (const float*)d_in[11];
    const float* w2  = (const float*)d_in[12];
    const float* b2  = (const float*)d_in[13];
    const float* g1  = (const float*)d_in[14];
    const float* be1 = (const float*)d_in[15];
    const float* g2  = (const float*)d_in[16];
    const float* be2 = (const float*)d_in[17];
    float* out = (float*)d_out;

    float *xn,*q,*k,*vT,*ctx,*x1,*hb,*sc,*wqT,*wkT,*wvT,*woT,*w1T,*w2T;
    cudaGetSymbolAddress((void**)&xn,  g_xn);
    cudaGetSymbolAddress((void**)&q,   g_q);
    cudaGetSymbolAddress((void**)&k,   g_k);
    cudaGetSymbolAddress((void**)&vT,  g_vT);
    cudaGetSymbolAddress((void**)&ctx, g_ctx);
    cudaGetSymbolAddress((void**)&x1,  g_x1);
    cudaGetSymbolAddress((void**)&hb,  g_h);
    cudaGetSymbolAddress((void**)&sc,  g_scores);
    cudaGetSymbolAddress((void**)&wqT, g_wqT);
    cudaGetSymbolAddress((void**)&wkT, g_wkT);
    cudaGetSymbolAddress((void**)&wvT, g_wvT);
    cudaGetSymbolAddress((void**)&woT, g_woT);
    cudaGetSymbolAddress((void**)&w1T, g_w1T);
    cudaGetSymbolAddress((void**)&w2T, g_w2T);

    dim3 tb(32, 8);
    transpose_kernel<<<dim3(DD/32,   DD/32),   tb>>>(wq, wqT, DD,   DD);
    transpose_kernel<<<dim3(DD/32,   DD/32),   tb>>>(wk, wkT, DD,   DD);
    transpose_kernel<<<dim3(DD/32,   DD/32),   tb>>>(wv, wvT, DD,   DD);
    transpose_kernel<<<dim3(DD/32,   DD/32),   tb>>>(wo, woT, DD,   DD);
    transpose_kernel<<<dim3(DFFN/32, DD/32),   tb>>>(w1, w1T, DD,   DFFN);
    transpose_kernel<<<dim3(DD/32,   DFFN/32), tb>>>(w2, w2T, DFFN, DD);

    // 1) LN1 (tf32-rounded output; only consumed by GEMMs)
    ln_kernel<<<NTOK, 256>>>(x, xn, g1, be1);

    // 2) Q, K projections; V stored transposed [b, d, s]
    run_gemm<128,4,4,4>(xn, wqT, q,  bq, nullptr, nullptr, NTOK, DD, DD, DD, DD, DD,
                        0,0,0,0,0,0, 1, 1.f, 0, 0, 1);
    run_gemm<128,4,4,4>(xn, wkT, k,  bk, nullptr, nullptr, NTOK, DD, DD, DD, DD, DD,
                        0,0,0,0,0,0, 1, 1.f, 0, 0, 1);
    run_gemm<128,4,4,4>(xn, wvT, vT, bv, nullptr, nullptr, NTOK, DD, DD, DD, DD, DD,
                        0,0,0,0,0,0, 1, 1.f, 0, 1, 1);

    // 3) scores = (Q @ K^T)/8, mask==0 -> -1.0   (fp32 out, softmax rounds later)
    run_gemm<128,4,4,4>(q, k, sc, nullptr, nullptr, msk,
                        SS, SS, DKK, DD, DD, SS,
                        (long)SS*DD, DKK, (long)SS*DD, DKK,
                        (long)HH*SS*SS, (long)SS*SS,
                        BB*HH, 0.125f, 0, 0, 0);

    // 4) softmax rows (tf32-rounded output)
    softmax_kernel<<<BB*HH*SS, 256>>>(sc);

    // 5) ctx = attn @ V  (B operand = vT rows, K-major)
    run_gemm<64,2,2,4>(sc, vT, ctx, nullptr, nullptr, nullptr,
                       SS, DKK, SS, SS, SS, DD,
                       (long)HH*SS*SS, (long)SS*SS,
                       (long)DD*SS, (long)DKK*SS,
                       (long)SS*DD, DKK,
                       BB*HH, 1.f, 0, 0, 1);

    // 6) x1 = x + ctx @ wo + bo (fp32)
    run_gemm<128,4,4,4>(ctx, woT, x1, bo, x, nullptr, NTOK, DD, DD, DD, DD, DD,
                        0,0,0,0,0,0, 1, 1.f, 0, 0, 0);

    // 7) LN2
    ln_kernel<<<NTOK, 256>>>(x1, xn, g2, be2);

    // 8) h = relu(xn @ w1 + b1) (tf32-rounded)
    run_gemm<128,4,4,4>(xn, w1T, hb, b1, nullptr, nullptr, NTOK, DFFN, DD, DD, DD, DFFN,
                        0,0,0,0,0,0, 1, 1.f, 1, 0, 1);

    // 9) out = x1 + h @ w2 + b2 (fp32)
    run_gemm<128,4,4,4>(hb, w2T, out, b2, x1, nullptr, NTOK, DD, DFFN, DFFN, DFFN, DD,
                        0,0,0,0,0,0, 1, 1.f, 0, 0, 0);
}

// round 6
// speedup vs baseline: 4.3384x; 1.4059x over previous
#include <cuda_runtime.h>
#include <cstdint>
#include <math.h>

#define BB   2
#define SS   2048
#define DD   1024
#define HH   16
#define DKK  64
#define DFFN 4096
#define NTOK (BB*SS)

// ---------------- persistent scratch (no runtime allocation) ----------------
__device__ float g_xn [NTOK*DD];
__device__ float g_q  [NTOK*DD];
__device__ float g_k  [NTOK*DD];
__device__ float g_vT [(size_t)BB*DD*SS];      // V transposed: [b, d, s]
__device__ float g_ctx[NTOK*DD];
__device__ float g_x1 [NTOK*DD];
__device__ float g_h  [NTOK*DFFN];
__device__ float g_wqT[DD*DD];
__device__ float g_wkT[DD*DD];
__device__ float g_wvT[DD*DD];
__device__ float g_woT[DD*DD];
__device__ float g_w1T[(size_t)DFFN*DD];
__device__ float g_w2T[(size_t)DD*DFFN];

// ---------------- helpers ----------------
__device__ __forceinline__ float tf32r(float x){
    uint32_t u; asm("cvt.rna.tf32.f32 %0, %1;" : "=r"(u) : "f"(x));
    return __uint_as_float(u);
}
__device__ __forceinline__ uint32_t smem_u32(const void* p){
    uint32_t a;
    asm("{ .reg .u64 t; cvta.to.shared.u64 t, %1; cvt.u32.u64 %0, t; }" : "=r"(a) : "l"(p));
    return a;
}
__device__ __forceinline__ void cp16(uint32_t dst, const float* src){
    asm volatile("cp.async.cg.shared.global [%0], [%1], 16;"
                 :: "r"(dst), "l"(__cvta_generic_to_global(src)) : "memory");
}
__device__ __forceinline__ void mma8(float* acc, const uint32_t* af, uint32_t b0, uint32_t b1){
    asm volatile(
        "mma.sync.aligned.m16n8k8.row.col.f32.tf32.tf32.f32 "
        "{%0,%1,%2,%3}, {%4,%5,%6,%7}, {%8,%9}, {%0,%1,%2,%3};"
        : "+f"(acc[0]), "+f"(acc[1]), "+f"(acc[2]), "+f"(acc[3])
        : "r"(af[0]), "r"(af[1]), "r"(af[2]), "r"(af[3]), "r"(b0), "r"(b1));
}

// ---------------- LayerNorm (ddof=1, /(std+eps)); output tf32-rounded ----------------
__global__ __launch_bounds__(256) void ln_kernel(
    const float* __restrict__ x, float* __restrict__ out,
    const float* __restrict__ g, const float* __restrict__ b)
{
    __shared__ float red[256];
    int row = blockIdx.x;
    int tid = threadIdx.x;
    const float* xr = x + (size_t)row * DD;

    float v[4]; float s = 0.f;
#pragma unroll
    for (int i = 0; i < 4; i++) { v[i] = xr[tid + i*256]; s += v[i]; }
    red[tid] = s; __syncthreads();
    for (int o = 128; o > 0; o >>= 1) { if (tid < o) red[tid] += red[tid+o]; __syncthreads(); }
    float mean = red[0] / (float)DD;
    __syncthreads();

    float vs = 0.f;
#pragma unroll
    for (int i = 0; i < 4; i++) { float d = v[i] - mean; vs += d*d; }
    red[tid] = vs; __syncthreads();
    for (int o = 128; o > 0; o >>= 1) { if (tid < o) red[tid] += red[tid+o]; __syncthreads(); }
    float var = red[0] / (float)(DD - 1);
    float inv = 1.f / (sqrtf(var) + 1e-6f);
    float g0 = g[0], b0 = b[0];
    float* orow = out + (size_t)row * DD;
#pragma unroll
    for (int i = 0; i < 4; i++)
        orow[tid + i*256] = tf32r(g0 * (v[i] - mean) * inv + b0);
}

// ---------------- weight transpose (tf32-rounded) ----------------
__global__ __launch_bounds__(256) void transpose_kernel(
    const float* __restrict__ in, float* __restrict__ out, int R, int Cc)
{
    __shared__ float t[32][33];
    int c0 = blockIdx.x * 32, r0 = blockIdx.y * 32;
    int x = threadIdx.x, y = threadIdx.y;      // block (32, 8)
#pragma unroll
    for (int i = y; i < 32; i += 8) t[i][x] = in[(size_t)(r0 + i) * Cc + c0 + x];
    __syncthreads();
#pragma unroll
    for (int i = y; i < 32; i += 8) out[(size_t)(c0 + i) * R + r0 + x] = tf32r(t[x][i]);
}

// ============================================================
// Fused flash attention (tf32 mma.sync), per CTA: 128 query rows of one (b,h).
// K-tiles of 128 keys; online softmax; P@V accumulated in registers.
// scores = (q.k)/8; mask==0 -> -1.0 (reference precedence bug).
// ============================================================
#define SQ_STRIDE 68
#define SV_STRIDE 132
static constexpr int FLASH_SMEM =
    (128*SQ_STRIDE + 128*SQ_STRIDE + 64*SV_STRIDE + 128*SV_STRIDE) * 4 + 128 * 4;

__global__ __launch_bounds__(256)
void flash_kernel(const float* __restrict__ q, const float* __restrict__ k,
                  const float* __restrict__ vT, const int* __restrict__ msk,
                  float* __restrict__ ctx)
{
    extern __shared__ float sm[];
    float* sQ = sm;                            // [128][68]
    float* sK = sQ + 128*SQ_STRIDE;            // [128][68]   key rows, dk cols
    float* sV = sK + 128*SQ_STRIDE;            // [64][132]   dk rows, key cols
    float* sP = sV + 64*SV_STRIDE;             // [128][132]  probs
    int*   sM = (int*)(sP + 128*SV_STRIDE);    // [128]

    const int tid = threadIdx.x;
    const int z  = blockIdx.y, bz = z >> 4, hz = z & 15;
    const int s0 = blockIdx.x * 128;
    const int warp = tid >> 5, lane = tid & 31;
    const int g = lane >> 2, qd = lane & 3;
    const int rowA = warp * 16;

    const float* qb = q  + ((size_t)(bz*SS + s0))*DD + hz*64;
    const float* kb = k  + ((size_t)bz*SS)*DD + hz*64;
    const float* vb = vT + (size_t)bz*DD*SS + (size_t)hz*64*SS;

    const uint32_t sQa = smem_u32(sQ), sKa = smem_u32(sK), sVa = smem_u32(sV);

    // Q tile (once)
#pragma unroll
    for (int p = 0; p < 8; p++){
        int slot = tid + p*256;
        int r = slot >> 4, c4 = slot & 15;
        cp16(sQa + (uint32_t)(r*SQ_STRIDE + c4*4)*4, qb + (size_t)r*DD + c4*4);
    }
    asm volatile("cp.async.commit_group;" ::: "memory");

    float m0 = -INFINITY, m1 = -INFINITY, l0 = 0.f, l1 = 0.f;
    float o[8][4];
#pragma unroll
    for (int nt = 0; nt < 8; nt++)
#pragma unroll
        for (int e = 0; e < 4; e++) o[nt][e] = 0.f;

    for (int kt = 0; kt < 16; kt++){
        __syncthreads();                       // previous tile fully consumed
        // K tile: [key][dk]
#pragma unroll
        for (int p = 0; p < 8; p++){
            int slot = tid + p*256;
            int r = slot >> 4, c4 = slot & 15;
            cp16(sKa + (uint32_t)(r*SQ_STRIDE + c4*4)*4,
                 kb + (size_t)(kt*128 + r)*DD + c4*4);
        }
        // V tile from vT: [dk][key]
#pragma unroll
        for (int p = 0; p < 8; p++){
            int slot = tid + p*256;
            int r = slot >> 5, c4 = slot & 31;
            cp16(sVa + (uint32_t)(r*SV_STRIDE + c4*4)*4,
                 vb + (size_t)r*SS + kt*128 + c4*4);
        }
        asm volatile("cp.async.commit_group;" ::: "memory");
        if (tid < 128) sM[tid] = msk[bz*SS + kt*128 + tid];
        asm volatile("cp.async.wait_group 0;" ::: "memory");
        __syncthreads();

        // ---- scores: 16 rows x 128 keys per warp ----
        float s[16][4];
#pragma unroll
        for (int nt = 0; nt < 16; nt++)
#pragma unroll
            for (int e = 0; e < 4; e++) s[nt][e] = 0.f;

#pragma unroll
        for (int ks = 0; ks < 64; ks += 8){
            uint32_t af[4];
            const uint32_t* ap  = (const uint32_t*)(sQ + (rowA + g    )*SQ_STRIDE + ks + qd);
            const uint32_t* ap8 = (const uint32_t*)(sQ + (rowA + g + 8)*SQ_STRIDE + ks + qd);
            af[0] = ap[0];  af[2] = ap[4];
            af[1] = ap8[0]; af[3] = ap8[4];
#pragma unroll
            for (int nt = 0; nt < 16; nt++){
                const uint32_t* bp = (const uint32_t*)(sK + (nt*8 + g)*SQ_STRIDE + ks + qd);
                mma8(s[nt], af, bp[0], bp[4]);
            }
        }

        // ---- scale + mask + tile max ----
        float tm0 = -INFINITY, tm1 = -INFINITY;
#pragma unroll
        for (int nt = 0; nt < 16; nt++){
            int mc0 = sM[nt*8 + 2*qd], mc1 = sM[nt*8 + 2*qd + 1];
            s[nt][0] = mc0 ? s[nt][0] * 0.125f : -1.0f;
            s[nt][1] = mc1 ? s[nt][1] * 0.125f : -1.0f;
            s[nt][2] = mc0 ? s[nt][2] * 0.125f : -1.0f;
            s[nt][3] = mc1 ? s[nt][3] * 0.125f : -1.0f;
            tm0 = fmaxf(tm0, fmaxf(s[nt][0], s[nt][1]));
            tm1 = fmaxf(tm1, fmaxf(s[nt][2], s[nt][3]));
        }
        tm0 = fmaxf(tm0, __shfl_xor_sync(0xffffffffu, tm0, 1));
        tm0 = fmaxf(tm0, __shfl_xor_sync(0xffffffffu, tm0, 2));
        tm1 = fmaxf(tm1, __shfl_xor_sync(0xffffffffu, tm1, 1));
        tm1 = fmaxf(tm1, __shfl_xor_sync(0xffffffffu, tm1, 2));

        float mn0 = fmaxf(m0, tm0), mn1 = fmaxf(m1, tm1);
        float a0 = __expf(m0 - mn0), a1 = __expf(m1 - mn1);

        // ---- exp, row sums, write P to smem ----
        float ts0 = 0.f, ts1 = 0.f;
        float* pr0 = sP + (rowA + g    )*SV_STRIDE + 2*qd;
        float* pr1 = sP + (rowA + g + 8)*SV_STRIDE + 2*qd;
#pragma unroll
        for (int nt = 0; nt < 16; nt++){
            float p0 = __expf(s[nt][0] - mn0), p1 = __expf(s[nt][1] - mn0);
            float p2 = __expf(s[nt][2] - mn1), p3 = __expf(s[nt][3] - mn1);
            ts0 += p0 + p1; ts1 += p2 + p3;
            *(float2*)(pr0 + nt*8) = make_float2(tf32r(p0), tf32r(p1));
            *(float2*)(pr1 + nt*8) = make_float2(tf32r(p2), tf32r(p3));
        }
        ts0 += __shfl_xor_sync(0xffffffffu, ts0, 1);
        ts0 += __shfl_xor_sync(0xffffffffu, ts0, 2);
        ts1 += __shfl_xor_sync(0xffffffffu, ts1, 1);
        ts1 += __shfl_xor_sync(0xffffffffu, ts1, 2);

        l0 = l0 * a0 + ts0;  l1 = l1 * a1 + ts1;
        m0 = mn0;  m1 = mn1;

#pragma unroll
        for (int nt = 0; nt < 8; nt++){
            o[nt][0] *= a0; o[nt][1] *= a0;
            o[nt][2] *= a1; o[nt][3] *= a1;
        }
        __syncwarp();

        // ---- P @ V ----
#pragma unroll
        for (int kk = 0; kk < 128; kk += 8){
            uint32_t af[4];
            const uint32_t* ap  = (const uint32_t*)(sP + (rowA + g    )*SV_STRIDE + kk + qd);
            const uint32_t* ap8 = (const uint32_t*)(sP + (rowA + g + 8)*SV_STRIDE + kk + qd);
            af[0] = ap[0];  af[2] = ap[4];
            af[1] = ap8[0]; af[3] = ap8[4];
#pragma unroll
            for (int nt = 0; nt < 8; nt++){
                const uint32_t* bp = (const uint32_t*)(sV + (nt*8 + g)*SV_STRIDE + kk + qd);
                mma8(o[nt], af, bp[0], bp[4]);
            }
        }
    }

    // ---- epilogue: normalize, tf32-round, write ctx [B,S,H,DK] ----
    float i0 = 1.f / l0, i1 = 1.f / l1;
    size_t r0i = ((size_t)(bz*SS + s0 + rowA + g    ))*DD + hz*64;
    size_t r1i = ((size_t)(bz*SS + s0 + rowA + g + 8))*DD + hz*64;
#pragma unroll
    for (int nt = 0; nt < 8; nt++){
        int c = nt*8 + 2*qd;
        ctx[r0i + c]     = tf32r(o[nt][0] * i0);
        ctx[r0i + c + 1] = tf32r(o[nt][1] * i0);
        ctx[r1i + c]     = tf32r(o[nt][2] * i1);
        ctx[r1i + c + 1] = tf32r(o[nt][3] * i1);
    }
}

// ============================================================
// tf32 mma.sync GEMM: C[128 x BN] per CTA = alpha*(A @ Bt^T) (+bias)(+resid)(relu)
// ============================================================
template<int BN, int WGX, int MT, int NT>
__global__ __launch_bounds__(256)
void mma_gemm(const float* __restrict__ A, const float* __restrict__ Bt,
              float* __restrict__ C, const float* __restrict__ bias,
              const float* __restrict__ resid,
              int K, int lda, int ldb, int ldc,
              float alpha, int relu, int storeT, int roundOut)
{
    extern __shared__ float sm[];
    constexpr int ASZ = 128 * 36;
    constexpr int BSZ = BN * 36;
    float* A0 = sm;
    float* B0 = sm + 2 * ASZ;

    const int tid = threadIdx.x;
    const float* Ab = A;
    const float* Bb = Bt;
    float*       Cb = C;
    const int rowStart = blockIdx.y * 128;
    const int colStart = blockIdx.x * BN;

    const uint32_t aBase = smem_u32(A0), bBase = smem_u32(B0);

    auto loadA = [&](int buf, int k0){
        uint32_t dst = aBase + (uint32_t)buf * (ASZ * 4);
#pragma unroll
        for (int p = 0; p < 4; p++){
            int slot = tid + p * 256;
            int r = slot >> 3, qq = slot & 7;
            cp16(dst + (uint32_t)(r * 36 + qq * 4) * 4,
                 Ab + (size_t)(rowStart + r) * lda + k0 + qq * 4);
        }
    };
    auto loadB = [&](int buf, int k0){
        uint32_t dst = bBase + (uint32_t)buf * (BSZ * 4);
#pragma unroll
        for (int p = 0; p < BN / 32; p++){
            int slot = tid + p * 256;
            int r = slot >> 3, qq = slot & 7;
            cp16(dst + (uint32_t)(r * 36 + qq * 4) * 4,
                 Bb + (size_t)(colStart + r) * ldb + k0 + qq * 4);
        }
    };

    const int warp = tid >> 5, lane = tid & 31;
    const int g = lane >> 2, qd = lane & 3;
    const int wy = warp / WGX, wx = warp % WGX;
    const int m0 = wy * MT * 16, n0 = wx * NT * 8;

    float acc[MT][NT][4];
#pragma unroll
    for (int mt = 0; mt < MT; mt++)
#pragma unroll
        for (int nt = 0; nt < NT; nt++)
#pragma unroll
            for (int e = 0; e < 4; e++) acc[mt][nt][e] = 0.f;

    const int nk = K >> 5;
    loadA(0, 0); loadB(0, 0);
    asm volatile("cp.async.commit_group;" ::: "memory");

    for (int s = 0; s < nk; s++){
        if (s + 1 < nk){ loadA((s + 1) & 1, (s + 1) * 32); loadB((s + 1) & 1, (s + 1) * 32); }
        asm volatile("cp.async.commit_group;" ::: "memory");
        asm volatile("cp.async.wait_group 1;" ::: "memory");
        __syncthreads();

        const float* As = A0 + (s & 1) * ASZ;
        const float* Bs = B0 + (s & 1) * BSZ;
#pragma unroll
        for (int ks = 0; ks < 32; ks += 8){
            uint32_t af[MT][4], bf[NT][2];
#pragma unroll
            for (int mt = 0; mt < MT; mt++){
                const uint32_t* ap  = (const uint32_t*)(As + (m0 + mt*16 + g    ) * 36 + ks + qd);
                const uint32_t* ap8 = (const uint32_t*)(As + (m0 + mt*16 + g + 8) * 36 + ks + qd);
                af[mt][0] = ap[0];  af[mt][2] = ap[4];
                af[mt][1] = ap8[0]; af[mt][3] = ap8[4];
            }
#pragma unroll
            for (int nt = 0; nt < NT; nt++){
                const uint32_t* bp = (const uint32_t*)(Bs + (n0 + nt*8 + g) * 36 + ks + qd);
                bf[nt][0] = bp[0]; bf[nt][1] = bp[4];
            }
#pragma unroll
            for (int mt = 0; mt < MT; mt++)
#pragma unroll
                for (int nt = 0; nt < NT; nt++)
                    mma8(acc[mt][nt], af[mt], bf[nt][0], bf[nt][1]);
        }
        __syncthreads();
    }

    // ---------------- epilogue ----------------
#pragma unroll
    for (int mt = 0; mt < MT; mt++)
#pragma unroll
        for (int nt = 0; nt < NT; nt++)
#pragma unroll
            for (int e = 0; e < 4; e++){
                int r = rowStart + m0 + mt * 16 + g + ((e >= 2) ? 8 : 0);
                int c = colStart + n0 + nt * 8 + qd * 2 + (e & 1);
                float v = alpha * acc[mt][nt][e];
                if (bias)  v += bias[c];
                if (resid) v += resid[(size_t)r * ldc + c];
                if (relu)  v = fmaxf(v, 0.f);
                if (roundOut) v = tf32r(v);
                if (!storeT) {
                    Cb[(size_t)r * ldc + c] = v;
                } else {
                    int bb = r >> 11;            // r / SS
                    int si = r & (SS - 1);
                    C[((size_t)bb * DD + c) * SS + si] = v;
                }
            }
}

// ---------------- host-side launcher ----------------
template<int BN, int WGX, int MT, int NT>
static void run_gemm(const float* A, const float* Bt, float* C,
                     const float* bias, const float* resid,
                     int M, int N, int K, int lda, int ldb, int ldc,
                     float alpha, int relu, int storeT, int roundOut)
{
    constexpr int SMEM = (2 * 128 * 36 + 2 * BN * 36) * 4;
    cudaFuncSetAttribute(mma_gemm<BN, WGX, MT, NT>,
                         cudaFuncAttributeMaxDynamicSharedMemorySize, SMEM);
    dim3 grid(N / BN, M / 128, 1);
    mma_gemm<BN, WGX, MT, NT><<<grid, 256, SMEM>>>(
        A, Bt, C, bias, resid, K, lda, ldb, ldc, alpha, relu, storeT, roundOut);
}

extern "C" void kernel_launch(void* const* d_in, const int* in_sizes, int n_in,
                              void* d_out, int out_size)
{
    const float* x   = (const float*)d_in[0];
    const int*   msk = (const int*)  d_in[1];
    const float* wq  = (const float*)d_in[2];
    const float* bq  = (const float*)d_in[3];
    const float* wk  = (const float*)d_in[4];
    const float* bk  = (const float*)d_in[5];
    const float* wv  = (const float*)d_in[6];
    const float* bv  = (const float*)d_in[7];
    const float* wo  = (const float*)d_in[8];
    const float* bo  = (const float*)d_in[9];
    const float* w1  = (const float*)d_in[10];
    const float* b1  = (const float*)d_in[11];
    const float* w2  = (const float*)d_in[12];
    const float* b2  = (const float*)d_in[13];
    const float* g1  = (const float*)d_in[14];
    const float* be1 = (const float*)d_in[15];
    const float* g2  = (const float*)d_in[16];
    const float* be2 = (const float*)d_in[17];
    float* out = (float*)d_out;

    float *xn,*q,*k,*vT,*ctx,*x1,*hb,*wqT,*wkT,*wvT,*woT,*w1T,*w2T;
    cudaGetSymbolAddress((void**)&xn,  g_xn);
    cudaGetSymbolAddress((void**)&q,   g_q);
    cudaGetSymbolAddress((void**)&k,   g_k);
    cudaGetSymbolAddress((void**)&vT,  g_vT);
    cudaGetSymbolAddress((void**)&ctx, g_ctx);
    cudaGetSymbolAddress((void**)&x1,  g_x1);
    cudaGetSymbolAddress((void**)&hb,  g_h);
    cudaGetSymbolAddress((void**)&wqT, g_wqT);
    cudaGetSymbolAddress((void**)&wkT, g_wkT);
    cudaGetSymbolAddress((void**)&wvT, g_wvT);
    cudaGetSymbolAddress((void**)&woT, g_woT);
    cudaGetSymbolAddress((void**)&w1T, g_w1T);
    cudaGetSymbolAddress((void**)&w2T, g_w2T);

    dim3 tb(32, 8);
    transpose_kernel<<<dim3(DD/32,   DD/32),   tb>>>(wq, wqT, DD,   DD);
    transpose_kernel<<<dim3(DD/32,   DD/32),   tb>>>(wk, wkT, DD,   DD);
    transpose_kernel<<<dim3(DD/32,   DD/32),   tb>>>(wv, wvT, DD,   DD);
    transpose_kernel<<<dim3(DD/32,   DD/32),   tb>>>(wo, woT, DD,   DD);
    transpose_kernel<<<dim3(DFFN/32, DD/32),   tb>>>(w1, w1T, DD,   DFFN);
    transpose_kernel<<<dim3(DD/32,   DFFN/32), tb>>>(w2, w2T, DFFN, DD);

    // 1) LN1 (tf32-rounded output)
    ln_kernel<<<NTOK, 256>>>(x, xn, g1, be1);

    // 2) Q, K projections (tf32-rounded); V stored transposed [b, d, s]
    run_gemm<128,4,4,4>(xn, wqT, q,  bq, nullptr, NTOK, DD, DD, DD, DD, DD, 1.f, 0, 0, 1);
    run_gemm<128,4,4,4>(xn, wkT, k,  bk, nullptr, NTOK, DD, DD, DD, DD, DD, 1.f, 0, 0, 1);
    run_gemm<128,4,4,4>(xn, wvT, vT, bv, nullptr, NTOK, DD, DD, DD, DD, DD, 1.f, 0, 1, 1);

    // 3) fused attention: QK^T/8 -> mask(-1) -> softmax -> @V
    {
        cudaFuncSetAttribute(flash_kernel, cudaFuncAttributeMaxDynamicSharedMemorySize,
                             FLASH_SMEM);
        dim3 grid(SS/128, BB*HH);
        flash_kernel<<<grid, 256, FLASH_SMEM>>>(q, k, vT, msk, ctx);
    }

    // 4) x1 = x + ctx @ wo + bo (fp32)
    run_gemm<128,4,4,4>(ctx, woT, x1, bo, x, NTOK, DD, DD, DD, DD, DD, 1.f, 0, 0, 0);

    // 5) LN2
    ln_kernel<<<NTOK, 256>>>(x1, xn, g2, be2);

    // 6) h = relu(xn @ w1 + b1) (tf32-rounded)
    run_gemm<128,4,4,4>(xn, w1T, hb, b1, nullptr, NTOK, DFFN, DD, DD, DD, DFFN, 1.f, 1, 0, 1);

    // 7) out = x1 + h @ w2 + b2 (fp32)
    run_gemm<128,4,4,4>(hb, w2T, out, b2, x1, NTOK, DD, DFFN, DFFN, DFFN, DD, 1.f, 0, 0, 0);
}